// round 1
// baseline (speedup 1.0000x reference)
#include <cuda_runtime.h>

// Problem constants
#define Kc    9
#define NCc   13
#define NAc   5
#define NBc   128
#define NHc   26
#define NWc   26
#define NTc   50
#define Lc    21          // 2K+3
#define NPIX  (NHc*NWc)   // 676
#define NANCH (NAc*NPIX)  // 3380
#define CH    (2*Kc+1+NCc) // 32

#define THf     80.0f
#define SILf    0.6f
#define OBJf    5.0f
// 1/(exp(2)-1)
#define INVC0   0.15651764274966574f

// Scratch (device globals — no allocation allowed)
__device__ float d_gtx[NBc*NTc*Kc];
__device__ float d_gty[NBc*NTc*Kc];
__device__ float d_txv[NBc*NTc*Kc];
__device__ float d_tyv[NBc*NTc*Kc];
__device__ float d_conft[NBc*NTc];
__device__ float d_tclsA[NBc*NTc];
__device__ int   d_codeA[NBc*NTc];
__device__ int   d_nvalid[NBc];

__constant__ float c_anch[10] = {1.482f,2.2412f,2.0501f,3.1265f,2.3946f,
                                 4.6891f,3.1018f,3.991f,3.4879f,5.8851f};

__device__ __forceinline__ float sigmoidf_(float x) { return 1.0f/(1.0f+expf(-x)); }

__global__ void zero_out_kernel(float* p) {
    if (threadIdx.x == 0 && blockIdx.x == 0) p[0] = 0.0f;
}

// One block per batch; thread t handles target t.
__global__ void region_prep(const float* __restrict__ out,
                            const float* __restrict__ tgt)
{
    int b = blockIdx.x;
    int t = threadIdx.x;
    __shared__ int sflag[NTc];
    if (t < NTc)
        sflag[t] = (tgt[(size_t)b*NTc*Lc + (size_t)t*Lc + 1] != 0.0f) ? 1 : 0;
    __syncthreads();
    if (t == 0) {
        int nv = NTc;
        for (int q = 0; q < NTc; ++q) if (!sflag[q]) { nv = q; break; }
        d_nvalid[b] = nv;
    }
    if (t >= NTc) return;

    const float* row = tgt + (size_t)b*NTc*Lc + (size_t)t*Lc;
    float gxr[Kc], gyr[Kc];
#pragma unroll
    for (int k = 0; k < Kc; ++k) { gxr[k] = row[1+2*k]; gyr[k] = row[2+2*k]; }

    int gi0 = (int)floorf(gxr[0]*(float)NWc);
    int gj0 = (int)floorf(gyr[0]*(float)NHc);
    gi0 = min(max(gi0, 0), NWc-1);
    gj0 = min(max(gj0, 0), NHc-1);

    int idx = b*NTc + t;
#pragma unroll
    for (int k = 0; k < Kc; ++k) {
        d_gtx[idx*Kc+k] = gxr[k]*640.0f;
        d_gty[idx*Kc+k] = gyr[k]*480.0f;
        d_txv[idx*Kc+k] = gxr[k]*(float)NWc - (float)gi0;
        d_tyv[idx*Kc+k] = gyr[k]*(float)NHc - (float)gj0;
    }

    // best anchor by IoU on (gw, gh); first max wins (strict >)
    float gw = row[Lc-2]*(float)NWc;
    float gh = row[Lc-1]*(float)NHc;
    float best = -1.0f; int bn = 0;
#pragma unroll
    for (int a = 0; a < NAc; ++a) {
        float aw = c_anch[2*a], ah = c_anch[2*a+1];
        float mw = fminf(aw, gw), mh = fminf(ah, gh);
        float inter = mw*mh;
        float iou = inter / (aw*ah + gw*gh - inter);
        if (iou > best) { best = iou; bn = a; }
    }
    d_codeA[idx] = bn*NPIX + gj0*NWc + gi0;
    d_tclsA[idx] = row[0];

    // conf_t: gather pred box from batch (b-1 mod NB), anchor NA-1, cell (gj0, gi0)
    int bp = (b + NBc - 1) % NBc;
    const float* cb = out + ((size_t)(bp*NAc + (NAc-1))*CH)*NPIX
                          + (size_t)(gj0*NWc + gi0);
    float acc = 0.0f;
#pragma unroll
    for (int k = 0; k < Kc; ++k) {
        float xv = cb[(2*k)*NPIX];
        float yv = cb[(2*k+1)*NPIX];
        if (k == 0) { xv = sigmoidf_(xv); yv = sigmoidf_(yv); }
        float px = (xv + (float)gi0) * (1.0f/(float)NWc);
        float py = (yv + (float)gj0) * (1.0f/(float)NHc);
        float dx = (px - gxr[k]) * 640.0f;
        float dy = (py - gyr[k]) * 480.0f;
        float d2 = fmaf(dx, dx, dy*dy);
        if (d2 < THf*THf) {
            float d = sqrtf(d2);
            acc += (expf(2.0f - d*0.025f) - 1.0f) * INVC0;
        }
    }
    d_conft[idx] = acc * (1.0f/(float)Kc);
}

// grid: (ceil(NANCH/256), NB) ; one thread per cell
__global__ __launch_bounds__(256)
void region_main(const float* __restrict__ out,
                 const int*   __restrict__ ep,
                 float* __restrict__ loss)
{
    int b    = blockIdx.y;
    int cell = blockIdx.x*256 + threadIdx.x;

    __shared__ float sgx[NTc*Kc], sgy[NTc*Kc], stx[NTc*Kc], sty[NTc*Kc];
    __shared__ float sconft[NTc], stcls[NTc];
    __shared__ int   scode[NTc];
    __shared__ int   snv;

    for (int i2 = threadIdx.x; i2 < NTc*Kc; i2 += 256) {
        int g = b*NTc*Kc + i2;
        sgx[i2] = d_gtx[g];
        sgy[i2] = d_gty[g];
        stx[i2] = d_txv[g];
        sty[i2] = d_tyv[g];
    }
    if (threadIdx.x < NTc) {
        sconft[threadIdx.x] = d_conft[b*NTc + threadIdx.x];
        stcls[threadIdx.x]  = d_tclsA[b*NTc + threadIdx.x];
        scode[threadIdx.x]  = d_codeA[b*NTc + threadIdx.x];
    }
    if (threadIdx.x == 0) snv = d_nvalid[b];
    __syncthreads();

    int doconf = (ep[0] > 15) ? 1 : 0;
    float contrib = 0.0f;

    if (cell < NANCH) {
        int a   = cell / NPIX;
        int pos = cell - a*NPIX;
        int jj  = pos / NWc;
        int ii  = pos - jj*NWc;
        const float* cb = out + ((size_t)(b*NAc + a)*CH)*NPIX + (size_t)pos;

        // predicted corner positions (pixel units), stop-gradient path
        float pxs[Kc], pys[Kc];
#pragma unroll
        for (int k = 0; k < Kc; ++k) {
            float xv = cb[(2*k)*NPIX];
            float yv = cb[(2*k+1)*NPIX];
            if (k == 0) { xv = sigmoidf_(xv); yv = sigmoidf_(yv); }
            pxs[k] = ((xv + (float)ii) * (1.0f/(float)NWc)) * 640.0f;
            pys[k] = ((yv + (float)jj) * (1.0f/(float)NHc)) * 480.0f;
        }

        int nv = snv;

        // cur_conf = max over valid targets of mean corner confidence
        float m = 0.0f;
        for (int t = 0; t < nv; ++t) {
            float acc = 0.0f;
            const float* gx = &sgx[t*Kc];
            const float* gy = &sgy[t*Kc];
#pragma unroll
            for (int k = 0; k < Kc; ++k) {
                float dx = pxs[k] - gx[k];
                float dy = pys[k] - gy[k];
                float d2 = fmaf(dx, dx, dy*dy);
                if (d2 < THf*THf) {
                    float d = sqrtf(d2);
                    acc += (expf(2.0f - d*0.025f) - 1.0f) * INVC0;
                }
            }
            m = fmaxf(m, acc);
        }
        float curconf = m * (1.0f/(float)Kc);

        // last valid target scattered onto this cell wins
        int win = -1;
        for (int t = nv-1; t >= 0; --t)
            if (scode[t] == cell) { win = t; break; }

        float conf = sigmoidf_(cb[(2*Kc)*NPIX]);

        if (win >= 0) {
            // coord loss (0.5 * COORD_S * sum of squared diffs, mask=1)
            float cl = 0.0f;
#pragma unroll
            for (int k = 0; k < Kc; ++k) {
                float xv = cb[(2*k)*NPIX];
                float yv = cb[(2*k+1)*NPIX];
                if (k == 0) { xv = sigmoidf_(xv); yv = sigmoidf_(yv); }
                float exd = xv - stx[win*Kc+k];
                float eyd = yv - sty[win*Kc+k];
                cl += exd*exd + eyd*eyd;
            }
            contrib = 0.5f*cl;

            // class cross-entropy (cls_mask = 1)
            float lg[NCc];
            float mx = -1e30f;
#pragma unroll
            for (int c = 0; c < NCc; ++c) {
                lg[c] = cb[(2*Kc+1+c)*NPIX];
                mx = fmaxf(mx, lg[c]);
            }
            float se = 0.0f;
#pragma unroll
            for (int c = 0; c < NCc; ++c) se += expf(lg[c]-mx);
            int lab = (int)stcls[win];
            lab = min(max(lab, 0), NCc-1);
            contrib += (mx + logf(se)) - lg[lab];

            if (doconf) {
                float dc = conf - sconft[win];
                contrib += 0.5f*OBJf*dc*dc;   // conf_mask = OBJ at object cell
            }
        } else {
            // noobj conf loss; mask 0 if cur_conf > SIL else NOOBJ=1
            if (doconf && !(curconf > SILf))
                contrib += 0.5f*conf*conf;
        }
    }

    // block reduction + atomic into scalar loss
    __shared__ float red[256];
    red[threadIdx.x] = contrib;
    __syncthreads();
#pragma unroll
    for (int s = 128; s > 0; s >>= 1) {
        if (threadIdx.x < s) red[threadIdx.x] += red[threadIdx.x + s];
        __syncthreads();
    }
    if (threadIdx.x == 0) atomicAdd(loss, red[0]);
}

extern "C" void kernel_launch(void* const* d_in, const int* in_sizes, int n_in,
                              void* d_out, int out_size)
{
    const float* out = (const float*)d_in[0];
    const float* tgt = (const float*)d_in[1];
    const int*   ep  = (const int*)d_in[2];
    float* loss = (float*)d_out;

    zero_out_kernel<<<1, 32>>>(loss);
    region_prep<<<NBc, 64>>>(out, tgt);
    dim3 g((NANCH + 255)/256, NBc);
    region_main<<<g, 256>>>(out, ep, loss);
}

// round 2
// speedup vs baseline: 2.0575x; 2.0575x over previous
#include <cuda_runtime.h>

// Problem constants
#define Kc    9
#define NCc   13
#define NAc   5
#define NBc   128
#define NHc   26
#define NWc   26
#define NTc   50
#define Lc    21          // 2K+3
#define NPIX  (NHc*NWc)   // 676
#define NANCH (NAc*NPIX)  // 3380
#define CH    (2*Kc+1+NCc) // 32

#define THf     80.0f
#define TH2f    6400.0f
#define SILf    0.6f
#define OBJf    5.0f
// 1/(exp(2)-1)
#define INVC0   0.15651764274966574f

// Scratch (device globals — no allocation allowed)
// Packed, NEGATED gt corner coords: per (b,t): 5 float4 = (-gx0,-gy0,-gx1,-gy1),... corner8 in [4].xy
__device__ float4 d_gtn[NBc*NTc*5];
__device__ float d_txv[NBc*NTc*Kc];
__device__ float d_tyv[NBc*NTc*Kc];
__device__ float d_conft[NBc*NTc];
__device__ float d_tclsA[NBc*NTc];
__device__ int   d_codeA[NBc*NTc];
__device__ int   d_nvalid[NBc];

__constant__ float c_anch[10] = {1.482f,2.2412f,2.0501f,3.1265f,2.3946f,
                                 4.6891f,3.1018f,3.991f,3.4879f,5.8851f};

__device__ __forceinline__ float sigmoidf_(float x) { return 1.0f/(1.0f+expf(-x)); }

// One block per batch; thread t handles target t. Also zeroes the loss scalar.
__global__ void region_prep(const float* __restrict__ out,
                            const float* __restrict__ tgt,
                            float* __restrict__ loss)
{
    int b = blockIdx.x;
    int t = threadIdx.x;
    if (b == 0 && t == 0) loss[0] = 0.0f;

    __shared__ int sflag[NTc];
    if (t < NTc)
        sflag[t] = (tgt[(size_t)b*NTc*Lc + (size_t)t*Lc + 1] != 0.0f) ? 1 : 0;
    __syncthreads();
    if (t == 0) {
        int nv = NTc;
        for (int q = 0; q < NTc; ++q) if (!sflag[q]) { nv = q; break; }
        d_nvalid[b] = nv;
    }
    if (t >= NTc) return;

    const float* row = tgt + (size_t)b*NTc*Lc + (size_t)t*Lc;
    float gxr[Kc], gyr[Kc];
#pragma unroll
    for (int k = 0; k < Kc; ++k) { gxr[k] = row[1+2*k]; gyr[k] = row[2+2*k]; }

    int gi0 = (int)floorf(gxr[0]*(float)NWc);
    int gj0 = (int)floorf(gyr[0]*(float)NHc);
    gi0 = min(max(gi0, 0), NWc-1);
    gj0 = min(max(gj0, 0), NHc-1);

    int idx = b*NTc + t;

    // packed negated pixel-space corners
    float gpx[Kc], gpy[Kc];
#pragma unroll
    for (int k = 0; k < Kc; ++k) {
        gpx[k] = gxr[k]*640.0f;
        gpy[k] = gyr[k]*480.0f;
        d_txv[idx*Kc+k] = gxr[k]*(float)NWc - (float)gi0;
        d_tyv[idx*Kc+k] = gyr[k]*(float)NHc - (float)gj0;
    }
    d_gtn[idx*5+0] = make_float4(-gpx[0], -gpy[0], -gpx[1], -gpy[1]);
    d_gtn[idx*5+1] = make_float4(-gpx[2], -gpy[2], -gpx[3], -gpy[3]);
    d_gtn[idx*5+2] = make_float4(-gpx[4], -gpy[4], -gpx[5], -gpy[5]);
    d_gtn[idx*5+3] = make_float4(-gpx[6], -gpy[6], -gpx[7], -gpy[7]);
    d_gtn[idx*5+4] = make_float4(-gpx[8], -gpy[8], 0.0f, 0.0f);

    // best anchor by IoU on (gw, gh); first max wins (strict >)
    float gw = row[Lc-2]*(float)NWc;
    float gh = row[Lc-1]*(float)NHc;
    float best = -1.0f; int bn = 0;
#pragma unroll
    for (int a = 0; a < NAc; ++a) {
        float aw = c_anch[2*a], ah = c_anch[2*a+1];
        float mw = fminf(aw, gw), mh = fminf(ah, gh);
        float inter = mw*mh;
        float iou = inter / (aw*ah + gw*gh - inter);
        if (iou > best) { best = iou; bn = a; }
    }
    d_codeA[idx] = bn*NPIX + gj0*NWc + gi0;
    d_tclsA[idx] = row[0];

    // conf_t: gather pred box from batch (b-1 mod NB), anchor NA-1, cell (gj0, gi0)
    int bp = (b + NBc - 1) % NBc;
    const float* cb = out + ((size_t)(bp*NAc + (NAc-1))*CH)*NPIX
                          + (size_t)(gj0*NWc + gi0);
    float acc = 0.0f;
#pragma unroll
    for (int k = 0; k < Kc; ++k) {
        float xv = cb[(2*k)*NPIX];
        float yv = cb[(2*k+1)*NPIX];
        if (k == 0) { xv = sigmoidf_(xv); yv = sigmoidf_(yv); }
        float px = (xv + (float)gi0) * (1.0f/(float)NWc);
        float py = (yv + (float)gj0) * (1.0f/(float)NHc);
        float dx = (px - gxr[k]) * 640.0f;
        float dy = (py - gyr[k]) * 480.0f;
        float d2 = fmaf(dx, dx, dy*dy);
        if (d2 < TH2f) {
            float d = sqrtf(d2);
            acc += (expf(2.0f - d*0.025f) - 1.0f) * INVC0;
        }
    }
    d_conft[idx] = acc * (1.0f/(float)Kc);
}

// grid: (ceil(NANCH/256), NB) ; one thread per cell
__global__ __launch_bounds__(256, 4)
void region_main(const float* __restrict__ out,
                 const int*   __restrict__ ep,
                 float* __restrict__ loss)
{
    int b    = blockIdx.y;
    int cell = blockIdx.x*256 + threadIdx.x;

    __shared__ float4 sgt[NTc*5];
    __shared__ float stx[NTc*Kc], sty[NTc*Kc];
    __shared__ float sconft[NTc], stcls[NTc];
    __shared__ int   scode[NTc];
    __shared__ int   snv;

    if (threadIdx.x < NTc*5)
        sgt[threadIdx.x] = d_gtn[b*NTc*5 + threadIdx.x];
    for (int i2 = threadIdx.x; i2 < NTc*Kc; i2 += 256) {
        stx[i2] = d_txv[b*NTc*Kc + i2];
        sty[i2] = d_tyv[b*NTc*Kc + i2];
    }
    if (threadIdx.x < NTc) {
        sconft[threadIdx.x] = d_conft[b*NTc + threadIdx.x];
        stcls[threadIdx.x]  = d_tclsA[b*NTc + threadIdx.x];
        scode[threadIdx.x]  = d_codeA[b*NTc + threadIdx.x];
    }
    if (threadIdx.x == 0) snv = d_nvalid[b];
    __syncthreads();

    int doconf = (ep[0] > 15) ? 1 : 0;
    float contrib = 0.0f;

    if (cell < NANCH) {
        int a   = cell / NPIX;
        int pos = cell - a*NPIX;
        int jj  = pos / NWc;
        int ii  = pos - jj*NWc;
        const float* cb = out + ((size_t)(b*NAc + a)*CH)*NPIX + (size_t)pos;

        // predicted corner positions (pixel units), stop-gradient path
        float pxs[Kc], pys[Kc];
#pragma unroll
        for (int k = 0; k < Kc; ++k) {
            float xv = cb[(2*k)*NPIX];
            float yv = cb[(2*k+1)*NPIX];
            if (k == 0) { xv = sigmoidf_(xv); yv = sigmoidf_(yv); }
            pxs[k] = ((xv + (float)ii) * (1.0f/(float)NWc)) * 640.0f;
            pys[k] = ((yv + (float)jj) * (1.0f/(float)NHc)) * 480.0f;
        }

        int nv = snv;

        // ---- cheap screen: a target can only reach mean-conf > 0.6 (sum > 5.4)
        // if >= 6 of its 9 corners are within TH (each corner conf <= 1).
        // Only then run the exact sqrt/exp evaluation (rare).
        float m = 0.0f;
        for (int t = 0; t < nv; ++t) {
            const float4* g4 = &sgt[t*5];
            float4 a0 = g4[0], a1 = g4[1], a2 = g4[2], a3 = g4[3], a4 = g4[4];
            float gnx[Kc] = {a0.x, a0.z, a1.x, a1.z, a2.x, a2.z, a3.x, a3.z, a4.x};
            float gny[Kc] = {a0.y, a0.w, a1.y, a1.w, a2.y, a2.w, a3.y, a3.w, a4.y};
            int cnt = 0;
#pragma unroll
            for (int k = 0; k < Kc; ++k) {
                float dx = pxs[k] + gnx[k];       // gnx = -gx
                float dy = pys[k] + gny[k];
                float d2 = fmaf(dx, dx, dy*dy);
                cnt += (d2 < TH2f) ? 1 : 0;
            }
            if (cnt >= 6) {
                float acc = 0.0f;
#pragma unroll
                for (int k = 0; k < Kc; ++k) {
                    float dx = pxs[k] + gnx[k];
                    float dy = pys[k] + gny[k];
                    float d2 = fmaf(dx, dx, dy*dy);
                    if (d2 < TH2f) {
                        float d = sqrtf(d2);
                        acc += (expf(2.0f - d*0.025f) - 1.0f) * INVC0;
                    }
                }
                m = fmaxf(m, acc);
            }
        }
        // m is the max corner-conf SUM over targets (only exact for targets that
        // could exceed threshold). mean > SIL  <=>  sum > 9*SIL.
        int over_sil = (m * (1.0f/(float)Kc)) > SILf;

        // last valid target scattered onto this cell wins
        int win = -1;
        for (int t = nv-1; t >= 0; --t)
            if (scode[t] == cell) { win = t; break; }

        if (win >= 0) {
            // coord loss (0.5 * COORD_S * sum of squared diffs, mask=1)
            float cl = 0.0f;
#pragma unroll
            for (int k = 0; k < Kc; ++k) {
                float xv = cb[(2*k)*NPIX];
                float yv = cb[(2*k+1)*NPIX];
                if (k == 0) { xv = sigmoidf_(xv); yv = sigmoidf_(yv); }
                float exd = xv - stx[win*Kc+k];
                float eyd = yv - sty[win*Kc+k];
                cl += exd*exd + eyd*eyd;
            }
            contrib = 0.5f*cl;

            // class cross-entropy (cls_mask = 1)
            float lg[NCc];
            float mx = -1e30f;
#pragma unroll
            for (int c = 0; c < NCc; ++c) {
                lg[c] = cb[(2*Kc+1+c)*NPIX];
                mx = fmaxf(mx, lg[c]);
            }
            float se = 0.0f;
#pragma unroll
            for (int c = 0; c < NCc; ++c) se += expf(lg[c]-mx);
            int lab = (int)stcls[win];
            lab = min(max(lab, 0), NCc-1);
            contrib += (mx + logf(se)) - lg[lab];

            if (doconf) {
                float conf = sigmoidf_(cb[(2*Kc)*NPIX]);
                float dc = conf - sconft[win];
                contrib += 0.5f*OBJf*dc*dc;   // conf_mask = OBJ at object cell
            }
        } else {
            // noobj conf loss; mask 0 if cur_conf > SIL else NOOBJ=1
            if (doconf && !over_sil) {
                float conf = sigmoidf_(cb[(2*Kc)*NPIX]);
                contrib += 0.5f*conf*conf;
            }
        }
    }

    // block reduction + atomic into scalar loss
    __shared__ float red[256];
    red[threadIdx.x] = contrib;
    __syncthreads();
#pragma unroll
    for (int s = 128; s > 0; s >>= 1) {
        if (threadIdx.x < s) red[threadIdx.x] += red[threadIdx.x + s];
        __syncthreads();
    }
    if (threadIdx.x == 0) atomicAdd(loss, red[0]);
}

extern "C" void kernel_launch(void* const* d_in, const int* in_sizes, int n_in,
                              void* d_out, int out_size)
{
    const float* out = (const float*)d_in[0];
    const float* tgt = (const float*)d_in[1];
    const int*   ep  = (const int*)d_in[2];
    float* loss = (float*)d_out;

    region_prep<<<NBc, 64>>>(out, tgt, loss);
    dim3 g((NANCH + 255)/256, NBc);
    region_main<<<g, 256>>>(out, ep, loss);
}

// round 3
// speedup vs baseline: 2.1016x; 1.0214x over previous
#include <cuda_runtime.h>

// Problem constants
#define Kc    9
#define NCc   13
#define NAc   5
#define NBc   128
#define NHc   26
#define NWc   26
#define NTc   50
#define Lc    21          // 2K+3
#define NPIX  (NHc*NWc)   // 676
#define NANCH (NAc*NPIX)  // 3380
#define CH    (2*Kc+1+NCc) // 32
#define NBMW  106          // ceil(3380/32)

#define THf     80.0f
#define TH2f    6400.0f
#define SILf    0.6f
#define OBJf    5.0f
// 1/(exp(2)-1)
#define INVC0   0.15651764274966574f

typedef unsigned long long ull;
typedef unsigned int uint;

// Scratch (device globals — no allocation allowed)
// Per (b,t): 28 floats, grouped for ulonglong2 (LDS.128) pair loads:
//  g in 0..3 (corner pair 2g,2g+1):  base=g*6:
//    [+0,+1]=m2gx pair  [+2,+3]=m2gy pair  [+4,+5]=G pair
//  [24]=m2gx8 [25]=m2gy8 [26]=G8 [27]=pad
// where m2gx = -2*gx_px, G = gx_px^2+gy_px^2-TH^2
__device__ __align__(16) float d_gt2[NBc*NTc*28];
__device__ float d_txv[NBc*NTc*Kc];
__device__ float d_tyv[NBc*NTc*Kc];
__device__ float d_conft[NBc*NTc];
__device__ float d_tclsA[NBc*NTc];
__device__ int   d_codeA[NBc*NTc];
__device__ int   d_nvalid[NBc];

__constant__ float c_anch[10] = {1.482f,2.2412f,2.0501f,3.1265f,2.3946f,
                                 4.6891f,3.1018f,3.991f,3.4879f,5.8851f};

__device__ __forceinline__ float sigmoidf_(float x) { return 1.0f/(1.0f+expf(-x)); }

__device__ __forceinline__ ull pack2(float lo, float hi) {
    ull r;
    asm("mov.b64 %0, {%1, %2};" : "=l"(r) : "f"(lo), "f"(hi));
    return r;
}
__device__ __forceinline__ ull fma2_(ull a, ull b, ull c) {
    ull d;
    asm("fma.rn.f32x2 %0, %1, %2, %3;" : "=l"(d) : "l"(a), "l"(b), "l"(c));
    return d;
}
__device__ __forceinline__ ull add2_(ull a, ull b) {
    ull d;
    asm("add.rn.f32x2 %0, %1, %2;" : "=l"(d) : "l"(a), "l"(b));
    return d;
}

// One block per batch; thread t handles target t. Also zeroes the loss scalar.
__global__ void region_prep(const float* __restrict__ out,
                            const float* __restrict__ tgt,
                            float* __restrict__ loss)
{
    int b = blockIdx.x;
    int t = threadIdx.x;
    if (b == 0 && t == 0) loss[0] = 0.0f;

    __shared__ int sflag[NTc];
    if (t < NTc)
        sflag[t] = (tgt[(size_t)b*NTc*Lc + (size_t)t*Lc + 1] != 0.0f) ? 1 : 0;
    __syncthreads();
    if (t == 0) {
        int nv = NTc;
        for (int q = 0; q < NTc; ++q) if (!sflag[q]) { nv = q; break; }
        d_nvalid[b] = nv;
    }
    if (t >= NTc) return;

    const float* row = tgt + (size_t)b*NTc*Lc + (size_t)t*Lc;
    float gxr[Kc], gyr[Kc];
#pragma unroll
    for (int k = 0; k < Kc; ++k) { gxr[k] = row[1+2*k]; gyr[k] = row[2+2*k]; }

    int gi0 = (int)floorf(gxr[0]*(float)NWc);
    int gj0 = (int)floorf(gyr[0]*(float)NHc);
    gi0 = min(max(gi0, 0), NWc-1);
    gj0 = min(max(gj0, 0), NHc-1);

    int idx = b*NTc + t;

    float gpx[Kc], gpy[Kc], m2x[Kc], m2y[Kc], Gk[Kc];
#pragma unroll
    for (int k = 0; k < Kc; ++k) {
        gpx[k] = gxr[k]*640.0f;
        gpy[k] = gyr[k]*480.0f;
        m2x[k] = -(gpx[k]+gpx[k]);
        m2y[k] = -(gpy[k]+gpy[k]);
        Gk[k]  = fmaf(gpx[k], gpx[k], fmaf(gpy[k], gpy[k], -TH2f));
        d_txv[idx*Kc+k] = gxr[k]*(float)NWc - (float)gi0;
        d_tyv[idx*Kc+k] = gyr[k]*(float)NHc - (float)gj0;
    }
    float* gt = &d_gt2[idx*28];
#pragma unroll
    for (int g = 0; g < 4; ++g) {
        gt[g*6+0] = m2x[2*g];  gt[g*6+1] = m2x[2*g+1];
        gt[g*6+2] = m2y[2*g];  gt[g*6+3] = m2y[2*g+1];
        gt[g*6+4] = Gk[2*g];   gt[g*6+5] = Gk[2*g+1];
    }
    gt[24] = m2x[8]; gt[25] = m2y[8]; gt[26] = Gk[8]; gt[27] = 0.0f;

    // best anchor by IoU on (gw, gh); first max wins (strict >)
    float gw = row[Lc-2]*(float)NWc;
    float gh = row[Lc-1]*(float)NHc;
    float best = -1.0f; int bn = 0;
#pragma unroll
    for (int a = 0; a < NAc; ++a) {
        float aw = c_anch[2*a], ah = c_anch[2*a+1];
        float mw = fminf(aw, gw), mh = fminf(ah, gh);
        float inter = mw*mh;
        float iou = inter / (aw*ah + gw*gh - inter);
        if (iou > best) { best = iou; bn = a; }
    }
    d_codeA[idx] = bn*NPIX + gj0*NWc + gi0;
    d_tclsA[idx] = row[0];

    // conf_t: gather pred box from batch (b-1 mod NB), anchor NA-1, cell (gj0, gi0)
    int bp = (b + NBc - 1) % NBc;
    const float* cb = out + ((size_t)(bp*NAc + (NAc-1))*CH)*NPIX
                          + (size_t)(gj0*NWc + gi0);
    float acc = 0.0f;
#pragma unroll
    for (int k = 0; k < Kc; ++k) {
        float xv = cb[(2*k)*NPIX];
        float yv = cb[(2*k+1)*NPIX];
        if (k == 0) { xv = sigmoidf_(xv); yv = sigmoidf_(yv); }
        float px = (xv + (float)gi0) * (1.0f/(float)NWc);
        float py = (yv + (float)gj0) * (1.0f/(float)NHc);
        float dx = (px - gxr[k]) * 640.0f;
        float dy = (py - gyr[k]) * 480.0f;
        float d2 = fmaf(dx, dx, dy*dy);
        if (d2 < TH2f) {
            float d = sqrtf(d2);
            acc += (expf(2.0f - d*0.025f) - 1.0f) * INVC0;
        }
    }
    d_conft[idx] = acc * (1.0f/(float)Kc);
}

// grid: (ceil(NANCH/256), NB) ; one thread per cell
__global__ __launch_bounds__(256)
void region_main(const float* __restrict__ out,
                 const int*   __restrict__ ep,
                 float* __restrict__ loss)
{
    int b   = blockIdx.y;
    int tid = threadIdx.x;
    int cell = blockIdx.x*256 + tid;

    __shared__ __align__(16) float sgt[NTc*28];
    __shared__ float stx[NTc*Kc], sty[NTc*Kc];
    __shared__ float sconft[NTc], stcls[NTc];
    __shared__ int   scode[NTc];
    __shared__ uint  sbm[NBMW];
    __shared__ float wred[8];
    __shared__ int   snv;

    // cooperative shared fills
    {
        const float4* src = (const float4*)&d_gt2[b*NTc*28];
        float4* dst = (float4*)sgt;
        for (int i2 = tid; i2 < NTc*28/4; i2 += 256) dst[i2] = src[i2];
    }
    for (int i2 = tid; i2 < NTc*Kc; i2 += 256) {
        stx[i2] = d_txv[b*NTc*Kc + i2];
        sty[i2] = d_tyv[b*NTc*Kc + i2];
    }
    if (tid < NBMW) sbm[tid] = 0u;
    if (tid == 0) snv = d_nvalid[b];
    if (tid < NTc) {
        sconft[tid] = d_conft[b*NTc + tid];
        stcls[tid]  = d_tclsA[b*NTc + tid];
        int code    = d_codeA[b*NTc + tid];
        scode[tid]  = code;
        if (tid < d_nvalid[b])
            atomicOr(&sbm[code >> 5], 1u << (code & 31));
    }
    __syncthreads();

    int doconf = (ep[0] > 15) ? 1 : 0;
    float contrib = 0.0f;

    if (cell < NANCH) {
        int a   = cell / NPIX;
        int pos = cell - a*NPIX;
        int jj  = pos / NWc;
        int ii  = pos - jj*NWc;
        const float* cb = out + ((size_t)(b*NAc + a)*CH)*NPIX + (size_t)pos;

        const float sx = 640.0f/26.0f;
        const float sy = 480.0f/26.0f;
        float fx = (float)ii * sx;
        float fy = (float)jj * sy;

        // per-cell: predicted corner positions (pixel units) + P = px^2+py^2
        float pxs[Kc], pys[Kc], Ps[Kc];
#pragma unroll
        for (int k = 0; k < Kc; ++k) {
            float xv = cb[(2*k)*NPIX];
            float yv = cb[(2*k+1)*NPIX];
            if (k == 0) { xv = sigmoidf_(xv); yv = sigmoidf_(yv); }
            float px = fmaf(xv, sx, fx);
            float py = fmaf(yv, sy, fy);
            pxs[k] = px; pys[k] = py;
            Ps[k]  = fmaf(px, px, py*py);
        }
        ull pxp[4], pyp[4], Pp[4];
#pragma unroll
        for (int g = 0; g < 4; ++g) {
            pxp[g] = pack2(pxs[2*g], pxs[2*g+1]);
            pyp[g] = pack2(pys[2*g], pys[2*g+1]);
            Pp[g]  = pack2(Ps[2*g],  Ps[2*g+1]);
        }
        float px8 = pxs[8], py8 = pys[8], P8 = Ps[8];

        int nv = snv;
        float m = 0.0f;

        for (int t = 0; t < nv; ++t) {
            const float* tp = &sgt[t*28];
            const ulonglong2* q = (const ulonglong2*)tp;
            ulonglong2 q0 = q[0], q1 = q[1], q2 = q[2];
            ulonglong2 q3 = q[3], q4 = q[4], q5 = q[5], q6 = q[6];

            // pair layout: q0=(m2gx01,m2gy01) q1=(G01,m2gx23) q2=(m2gy23,G23)
            //              q3=(m2gx45,m2gy45) q4=(G45,m2gx67) q5=(m2gy67,G67)
            //              q6=((m2gx8,m2gy8),(G8,pad))
            ull d0 = add2_(fma2_(pxp[0], q0.x, q1.x), fma2_(pyp[0], q0.y, Pp[0]));
            ull d1 = add2_(fma2_(pxp[1], q1.y, q2.y), fma2_(pyp[1], q2.x, Pp[1]));
            ull d2p = add2_(fma2_(pxp[2], q3.x, q4.x), fma2_(pyp[2], q3.y, Pp[2]));
            ull d3 = add2_(fma2_(pxp[3], q4.y, q5.y), fma2_(pyp[3], q5.x, Pp[3]));
            // corner 8 scalar
            float m2gx8 = __uint_as_float((uint)q6.x);
            float m2gy8 = __uint_as_float((uint)(q6.x >> 32));
            float G8    = __uint_as_float((uint)q6.y);
            float d8 = fmaf(px8, m2gx8, G8) + fmaf(py8, m2gy8, P8);

            // count corners with d^2 < TH^2  (sign bits of d2m)
            uint cnt = ((uint)d0 >> 31) + (uint)(d0 >> 63)
                     + ((uint)d1 >> 31) + (uint)(d1 >> 63)
                     + ((uint)d2p >> 31) + (uint)(d2p >> 63)
                     + ((uint)d3 >> 31) + (uint)(d3 >> 63)
                     + (__float_as_uint(d8) >> 31);

            // a target can only reach mean-conf > 0.6 (sum > 5.4) if >= 6
            // corners are within TH (each corner conf <= 1). Rare.
            if (cnt >= 6) {
                float acc = 0.0f;
#pragma unroll
                for (int k = 0; k < Kc; ++k) {
                    int g = k >> 1, r = k & 1;
                    float mgx = (k < 8) ? tp[g*6+r]   : tp[24];
                    float mgy = (k < 8) ? tp[g*6+2+r] : tp[25];
                    float xv = cb[(2*k)*NPIX];
                    float yv = cb[(2*k+1)*NPIX];
                    if (k == 0) { xv = sigmoidf_(xv); yv = sigmoidf_(yv); }
                    float px = fmaf(xv, sx, fx);
                    float py = fmaf(yv, sy, fy);
                    float dx = fmaf(0.5f, mgx, px);   // = px - gx (exact)
                    float dy = fmaf(0.5f, mgy, py);
                    float dd2 = fmaf(dx, dx, dy*dy);
                    if (dd2 < TH2f) {
                        float d = sqrtf(dd2);
                        acc += (expf(2.0f - d*0.025f) - 1.0f) * INVC0;
                    }
                }
                m = fmaxf(m, acc);
            }
        }
        int over_sil = (m * (1.0f/(float)Kc)) > SILf;

        // winner lookup: bitmap first (rare hit), then scan descending
        int win = -1;
        if (sbm[cell >> 5] & (1u << (cell & 31))) {
            for (int t = nv-1; t >= 0; --t)
                if (scode[t] == cell) { win = t; break; }
        }

        if (win >= 0) {
            // coord loss (0.5 * COORD_S * sum of squared diffs, mask=1)
            float cl = 0.0f;
#pragma unroll
            for (int k = 0; k < Kc; ++k) {
                float xv = cb[(2*k)*NPIX];
                float yv = cb[(2*k+1)*NPIX];
                if (k == 0) { xv = sigmoidf_(xv); yv = sigmoidf_(yv); }
                float exd = xv - stx[win*Kc+k];
                float eyd = yv - sty[win*Kc+k];
                cl += exd*exd + eyd*eyd;
            }
            contrib = 0.5f*cl;

            // class cross-entropy (cls_mask = 1)
            float lg[NCc];
            float mx = -1e30f;
#pragma unroll
            for (int c = 0; c < NCc; ++c) {
                lg[c] = cb[(2*Kc+1+c)*NPIX];
                mx = fmaxf(mx, lg[c]);
            }
            float se = 0.0f;
#pragma unroll
            for (int c = 0; c < NCc; ++c) se += expf(lg[c]-mx);
            int lab = (int)stcls[win];
            lab = min(max(lab, 0), NCc-1);
            contrib += (mx + logf(se)) - lg[lab];

            if (doconf) {
                float conf = sigmoidf_(cb[(2*Kc)*NPIX]);
                float dc = conf - sconft[win];
                contrib += 0.5f*OBJf*dc*dc;   // conf_mask = OBJ at object cell
            }
        } else {
            // noobj conf loss; mask 0 if cur_conf > SIL else NOOBJ=1
            if (doconf && !over_sil) {
                float conf = sigmoidf_(cb[(2*Kc)*NPIX]);
                contrib += 0.5f*conf*conf;
            }
        }
    }

    // warp-shuffle reduction + one atomic per block
#pragma unroll
    for (int off = 16; off > 0; off >>= 1)
        contrib += __shfl_down_sync(0xFFFFFFFFu, contrib, off);
    int lane = tid & 31, wid = tid >> 5;
    if (lane == 0) wred[wid] = contrib;
    __syncthreads();
    if (tid < 8) {
        float v = wred[tid];
#pragma unroll
        for (int off = 4; off > 0; off >>= 1)
            v += __shfl_down_sync(0xFFu, v, off);
        if (tid == 0) atomicAdd(loss, v);
    }
}

extern "C" void kernel_launch(void* const* d_in, const int* in_sizes, int n_in,
                              void* d_out, int out_size)
{
    const float* out = (const float*)d_in[0];
    const float* tgt = (const float*)d_in[1];
    const int*   ep  = (const int*)d_in[2];
    float* loss = (float*)d_out;

    region_prep<<<NBc, 64>>>(out, tgt, loss);
    dim3 g((NANCH + 255)/256, NBc);
    region_main<<<g, 256>>>(out, ep, loss);
}

// round 4
// speedup vs baseline: 2.6056x; 1.2399x over previous
#include <cuda_runtime.h>

// Problem constants
#define Kc    9
#define NCc   13
#define NAc   5
#define NBc   128
#define NHc   26
#define NWc   26
#define NTc   50
#define Lc    21          // 2K+3
#define NPIX  (NHc*NWc)   // 676
#define NANCH (NAc*NPIX)  // 3380
#define CH    (2*Kc+1+NCc) // 32
#define NBMW  106          // ceil(3380/32)

#define THf     80.0f
#define TH2f    6400.0f
#define SILf    0.6f
#define OBJf    5.0f
// 1/(exp(2)-1)
#define INVC0   0.15651764274966574f

typedef unsigned long long ull;
typedef unsigned int uint;

// Scratch (device globals — no allocation allowed)
// Per (b,t): 28 floats, grouped for ulonglong2 (LDS.128) pair loads:
//  g in 0..3 (corner pair 2g,2g+1):  base=g*6:
//    [+0,+1]=m2gx pair  [+2,+3]=m2gy pair  [+4,+5]=G pair
//  [24]=m2gx8 [25]=m2gy8 [26]=G8 [27]=pad
// where m2gx = -2*gx_px, G = gx_px^2+gy_px^2-TH^2
__device__ __align__(16) float d_gt2[NBc*NTc*28];
__device__ float d_txv[NBc*NTc*Kc];
__device__ float d_tyv[NBc*NTc*Kc];
__device__ float d_conft[NBc*NTc];
__device__ float d_tclsA[NBc*NTc];
__device__ int   d_codeA[NBc*NTc];
__device__ int   d_nvalid[NBc];

__constant__ float c_anch[10] = {1.482f,2.2412f,2.0501f,3.1265f,2.3946f,
                                 4.6891f,3.1018f,3.991f,3.4879f,5.8851f};

__device__ __forceinline__ float sigmoidf_(float x) { return 1.0f/(1.0f+expf(-x)); }

__device__ __forceinline__ ull pack2(float lo, float hi) {
    ull r;
    asm("mov.b64 %0, {%1, %2};" : "=l"(r) : "f"(lo), "f"(hi));
    return r;
}
__device__ __forceinline__ ull fma2_(ull a, ull b, ull c) {
    ull d;
    asm("fma.rn.f32x2 %0, %1, %2, %3;" : "=l"(d) : "l"(a), "l"(b), "l"(c));
    return d;
}
__device__ __forceinline__ ull add2_(ull a, ull b) {
    ull d;
    asm("add.rn.f32x2 %0, %1, %2;" : "=l"(d) : "l"(a), "l"(b));
    return d;
}
__device__ __forceinline__ uint sgn2(ull d) {
    return ((uint)d >> 31) + ((uint)(d >> 32) >> 31);
}

// One block per batch; thread t handles target t. Also zeroes the loss scalar.
__global__ void region_prep(const float* __restrict__ out,
                            const float* __restrict__ tgt,
                            float* __restrict__ loss)
{
    int b = blockIdx.x;
    int t = threadIdx.x;
    if (b == 0 && t == 0) loss[0] = 0.0f;

    __shared__ int sflag[NTc];
    if (t < NTc)
        sflag[t] = (tgt[(size_t)b*NTc*Lc + (size_t)t*Lc + 1] != 0.0f) ? 1 : 0;
    __syncthreads();
    if (t == 0) {
        int nv = NTc;
        for (int q = 0; q < NTc; ++q) if (!sflag[q]) { nv = q; break; }
        d_nvalid[b] = nv;
    }
    if (t >= NTc) return;

    const float* row = tgt + (size_t)b*NTc*Lc + (size_t)t*Lc;
    float gxr[Kc], gyr[Kc];
#pragma unroll
    for (int k = 0; k < Kc; ++k) { gxr[k] = row[1+2*k]; gyr[k] = row[2+2*k]; }

    int gi0 = (int)floorf(gxr[0]*(float)NWc);
    int gj0 = (int)floorf(gyr[0]*(float)NHc);
    gi0 = min(max(gi0, 0), NWc-1);
    gj0 = min(max(gj0, 0), NHc-1);

    int idx = b*NTc + t;

    float gpx[Kc], gpy[Kc], m2x[Kc], m2y[Kc], Gk[Kc];
#pragma unroll
    for (int k = 0; k < Kc; ++k) {
        gpx[k] = gxr[k]*640.0f;
        gpy[k] = gyr[k]*480.0f;
        m2x[k] = -(gpx[k]+gpx[k]);
        m2y[k] = -(gpy[k]+gpy[k]);
        Gk[k]  = fmaf(gpx[k], gpx[k], fmaf(gpy[k], gpy[k], -TH2f));
        d_txv[idx*Kc+k] = gxr[k]*(float)NWc - (float)gi0;
        d_tyv[idx*Kc+k] = gyr[k]*(float)NHc - (float)gj0;
    }
    float* gt = &d_gt2[idx*28];
#pragma unroll
    for (int g = 0; g < 4; ++g) {
        gt[g*6+0] = m2x[2*g];  gt[g*6+1] = m2x[2*g+1];
        gt[g*6+2] = m2y[2*g];  gt[g*6+3] = m2y[2*g+1];
        gt[g*6+4] = Gk[2*g];   gt[g*6+5] = Gk[2*g+1];
    }
    gt[24] = m2x[8]; gt[25] = m2y[8]; gt[26] = Gk[8]; gt[27] = 0.0f;

    // best anchor by IoU on (gw, gh); first max wins (strict >)
    float gw = row[Lc-2]*(float)NWc;
    float gh = row[Lc-1]*(float)NHc;
    float best = -1.0f; int bn = 0;
#pragma unroll
    for (int a = 0; a < NAc; ++a) {
        float aw = c_anch[2*a], ah = c_anch[2*a+1];
        float mw = fminf(aw, gw), mh = fminf(ah, gh);
        float inter = mw*mh;
        float iou = inter / (aw*ah + gw*gh - inter);
        if (iou > best) { best = iou; bn = a; }
    }
    d_codeA[idx] = bn*NPIX + gj0*NWc + gi0;
    d_tclsA[idx] = row[0];

    // conf_t: gather pred box from batch (b-1 mod NB), anchor NA-1, cell (gj0, gi0)
    int bp = (b + NBc - 1) % NBc;
    const float* cb = out + ((size_t)(bp*NAc + (NAc-1))*CH)*NPIX
                          + (size_t)(gj0*NWc + gi0);
    float acc = 0.0f;
#pragma unroll
    for (int k = 0; k < Kc; ++k) {
        float xv = cb[(2*k)*NPIX];
        float yv = cb[(2*k+1)*NPIX];
        if (k == 0) { xv = sigmoidf_(xv); yv = sigmoidf_(yv); }
        float px = (xv + (float)gi0) * (1.0f/(float)NWc);
        float py = (yv + (float)gj0) * (1.0f/(float)NHc);
        float dx = (px - gxr[k]) * 640.0f;
        float dy = (py - gyr[k]) * 480.0f;
        float d2 = fmaf(dx, dx, dy*dy);
        if (d2 < TH2f) {
            float d = sqrtf(d2);
            acc += (expf(2.0f - d*0.025f) - 1.0f) * INVC0;
        }
    }
    d_conft[idx] = acc * (1.0f/(float)Kc);
}

// grid: (ceil(NANCH/256), NB) ; one thread per cell
__global__ __launch_bounds__(256, 4)
void region_main(const float* __restrict__ out,
                 const int*   __restrict__ ep,
                 float* __restrict__ loss)
{
    int b   = blockIdx.y;
    int tid = threadIdx.x;
    int cell = blockIdx.x*256 + tid;

    __shared__ __align__(16) float sgt[NTc*28];
    __shared__ float sconft[NTc], stcls[NTc];
    __shared__ int   scode[NTc];
    __shared__ uint  sbm[NBMW];
    __shared__ float wred[8];
    __shared__ int   snv;

    // cooperative shared fills + bitmap zero
    {
        const float4* src = (const float4*)&d_gt2[b*NTc*28];
        float4* dst = (float4*)sgt;
        for (int i2 = tid; i2 < NTc*28/4; i2 += 256) dst[i2] = src[i2];
    }
    if (tid < NBMW) sbm[tid] = 0u;
    if (tid == 0) snv = d_nvalid[b];
    if (tid < NTc) {
        sconft[tid] = d_conft[b*NTc + tid];
        stcls[tid]  = d_tclsA[b*NTc + tid];
        scode[tid]  = d_codeA[b*NTc + tid];
    }
    __syncthreads();      // bitmap fully zeroed + scode/snv visible
    if (tid < NTc && tid < snv) {
        int code = scode[tid];
        atomicOr(&sbm[code >> 5], 1u << (code & 31));
    }
    __syncthreads();

    int doconf = (ep[0] > 15) ? 1 : 0;
    float contrib = 0.0f;

    if (cell < NANCH) {
        int a   = cell / NPIX;
        int pos = cell - a*NPIX;
        int jj  = pos / NWc;
        int ii  = pos - jj*NWc;
        const float* cb = out + ((size_t)(b*NAc + a)*CH)*NPIX + (size_t)pos;

        const float sx = 640.0f/26.0f;
        const float sy = 480.0f/26.0f;
        float fx = (float)ii * sx;
        float fy = (float)jj * sy;

        // per-cell packed state only (no scalar duplicates -> low regs)
        ull pxp[4], pyp[4], Pp[4];
#pragma unroll
        for (int g = 0; g < 4; ++g) {
            float xv0 = cb[(4*g+0)*NPIX];
            float yv0 = cb[(4*g+1)*NPIX];
            float xv1 = cb[(4*g+2)*NPIX];
            float yv1 = cb[(4*g+3)*NPIX];
            if (g == 0) { xv0 = sigmoidf_(xv0); yv0 = sigmoidf_(yv0); }
            float px0 = fmaf(xv0, sx, fx), py0 = fmaf(yv0, sy, fy);
            float px1 = fmaf(xv1, sx, fx), py1 = fmaf(yv1, sy, fy);
            pxp[g] = pack2(px0, px1);
            pyp[g] = pack2(py0, py1);
            Pp[g]  = pack2(fmaf(px0, px0, py0*py0), fmaf(px1, px1, py1*py1));
        }
        float px8 = fmaf(cb[16*NPIX], sx, fx);
        float py8 = fmaf(cb[17*NPIX], sy, fy);
        float P8  = fmaf(px8, px8, py8*py8);

        int nv = snv;
        float m = 0.0f;

        for (int t = 0; t < nv; ++t) {
            const float* tp = &sgt[t*28];
            const ulonglong2* q = (const ulonglong2*)tp;
            // pairs 0,1 first: cnt>=6 requires >=1 of corners 0..3 inside
            ulonglong2 q0 = q[0], q1 = q[1], q2 = q[2];
            ull d0 = add2_(fma2_(pxp[0], q0.x, q1.x), fma2_(pyp[0], q0.y, Pp[0]));
            ull d1 = add2_(fma2_(pxp[1], q1.y, q2.y), fma2_(pyp[1], q2.x, Pp[1]));
            uint any01 = ((uint)d0) | ((uint)(d0 >> 32)) |
                         ((uint)d1) | ((uint)(d1 >> 32));
            if ((int)any01 >= 0) continue;   // no sign bit among corners 0..3

            ulonglong2 q3 = q[3], q4 = q[4], q5 = q[5], q6 = q[6];
            ull d2p = add2_(fma2_(pxp[2], q3.x, q4.x), fma2_(pyp[2], q3.y, Pp[2]));
            ull d3  = add2_(fma2_(pxp[3], q4.y, q5.y), fma2_(pyp[3], q5.x, Pp[3]));
            float m2gx8 = __uint_as_float((uint)q6.x);
            float m2gy8 = __uint_as_float((uint)(q6.x >> 32));
            float G8    = __uint_as_float((uint)q6.y);
            float d8 = fmaf(px8, m2gx8, G8) + fmaf(py8, m2gy8, P8);

            uint cnt = sgn2(d0) + sgn2(d1) + sgn2(d2p) + sgn2(d3)
                     + (__float_as_uint(d8) >> 31);

            // mean-conf > 0.6 (sum > 5.4) requires >= 6 corners within TH
            // (each corner conf <= 1). Exact eval only then (rare).
            if (cnt >= 6) {
                float acc = 0.0f;
#pragma unroll
                for (int k = 0; k < Kc; ++k) {
                    int g = k >> 1, r = k & 1;
                    float mgx = (k < 8) ? tp[g*6+r]   : tp[24];
                    float mgy = (k < 8) ? tp[g*6+2+r] : tp[25];
                    float xv = cb[(2*k)*NPIX];
                    float yv = cb[(2*k+1)*NPIX];
                    if (k == 0) { xv = sigmoidf_(xv); yv = sigmoidf_(yv); }
                    float px = fmaf(xv, sx, fx);
                    float py = fmaf(yv, sy, fy);
                    float dx = fmaf(0.5f, mgx, px);   // = px - gx (exact)
                    float dy = fmaf(0.5f, mgy, py);
                    float dd2 = fmaf(dx, dx, dy*dy);
                    if (dd2 < TH2f) {
                        float d = sqrtf(dd2);
                        acc += (expf(2.0f - d*0.025f) - 1.0f) * INVC0;
                    }
                }
                m = fmaxf(m, acc);
            }
        }
        int over_sil = (m * (1.0f/(float)Kc)) > SILf;

        // winner lookup: bitmap first (rare hit), then scan descending
        int win = -1;
        if (sbm[cell >> 5] & (1u << (cell & 31))) {
            for (int t = nv-1; t >= 0; --t)
                if (scode[t] == cell) { win = t; break; }
        }

        if (win >= 0) {
            const float* txp = &d_txv[(b*NTc + win)*Kc];
            const float* typ = &d_tyv[(b*NTc + win)*Kc];
            // coord loss (0.5 * COORD_S * sum of squared diffs, mask=1)
            float cl = 0.0f;
#pragma unroll
            for (int k = 0; k < Kc; ++k) {
                float xv = cb[(2*k)*NPIX];
                float yv = cb[(2*k+1)*NPIX];
                if (k == 0) { xv = sigmoidf_(xv); yv = sigmoidf_(yv); }
                float exd = xv - txp[k];
                float eyd = yv - typ[k];
                cl += exd*exd + eyd*eyd;
            }
            contrib = 0.5f*cl;

            // class cross-entropy (cls_mask = 1)
            float lg[NCc];
            float mx = -1e30f;
#pragma unroll
            for (int c = 0; c < NCc; ++c) {
                lg[c] = cb[(2*Kc+1+c)*NPIX];
                mx = fmaxf(mx, lg[c]);
            }
            float se = 0.0f;
#pragma unroll
            for (int c = 0; c < NCc; ++c) se += expf(lg[c]-mx);
            int lab = (int)stcls[win];
            lab = min(max(lab, 0), NCc-1);
            contrib += (mx + logf(se)) - lg[lab];

            if (doconf) {
                float conf = sigmoidf_(cb[(2*Kc)*NPIX]);
                float dc = conf - sconft[win];
                contrib += 0.5f*OBJf*dc*dc;   // conf_mask = OBJ at object cell
            }
        } else {
            // noobj conf loss; mask 0 if cur_conf > SIL else NOOBJ=1
            if (doconf && !over_sil) {
                float conf = sigmoidf_(cb[(2*Kc)*NPIX]);
                contrib += 0.5f*conf*conf;
            }
        }
    }

    // warp-shuffle reduction + one atomic per block
#pragma unroll
    for (int off = 16; off > 0; off >>= 1)
        contrib += __shfl_down_sync(0xFFFFFFFFu, contrib, off);
    int lane = tid & 31, wid = tid >> 5;
    if (lane == 0) wred[wid] = contrib;
    __syncthreads();
    if (tid < 8) {
        float v = wred[tid];
#pragma unroll
        for (int off = 4; off > 0; off >>= 1)
            v += __shfl_down_sync(0xFFu, v, off);
        if (tid == 0) atomicAdd(loss, v);
    }
}

extern "C" void kernel_launch(void* const* d_in, const int* in_sizes, int n_in,
                              void* d_out, int out_size)
{
    const float* out = (const float*)d_in[0];
    const float* tgt = (const float*)d_in[1];
    const int*   ep  = (const int*)d_in[2];
    float* loss = (float*)d_out;

    region_prep<<<NBc, 64>>>(out, tgt, loss);
    dim3 g((NANCH + 255)/256, NBc);
    region_main<<<g, 256>>>(out, ep, loss);
}